// round 7
// baseline (speedup 1.0000x reference)
#include <cuda_runtime.h>
#include <math.h>

#define LSEQ 65536
#define CS 128
#define NC 512   // NC*CS == LSEQ

// ---------------- scratch (static __device__, allocation-free) ----------------
__device__ float  g_seq[LSEQ * 12];        // seq[t][d]
__device__ float4 g_gi[2][LSEQ * 6];       // per-dir packed gate inputs {0.5*gr, 0.5*gz, gn, 0}
__device__ float  g_cA[NC * 384];          // per-chunk affine A
__device__ float  g_cB[NC * 384];          // per-chunk affine B
__device__ float  g_hout[12];              // hf[6], hb[6]
__device__ float  g_yb0[6];                // backward GRU output at step 0

__device__ __forceinline__ float fsig(float x) {
    return __fdividef(1.f, 1.f + __expf(-x));
}
__device__ __forceinline__ float fsilu(float x) {
    return x * fsig(x);
}
// single-MUFU tanh (sm_75+); used only in the GRU hot loop
__device__ __forceinline__ float tapx(float x) {
    float y;
    asm("tanh.approx.f32 %0, %1;" : "=f"(y) : "f"(x));
    return y;
}
// 6-element dot + base, tree-structured (depth ~4 ops instead of 6)
__device__ __forceinline__ float dot6(const float* W, const float* h, float base) {
    float a = fmaf(W[0], h[0], base);
    a = fmaf(W[1], h[1], a);
    float b = W[2] * h[2];
    b = fmaf(W[3], h[3], b);
    float c = W[4] * h[4];
    c = fmaf(W[5], h[5], c);
    return a + (b + c);
}

// ---------------- Stage A: fused conv1x1 -> bn -> relu -> conv1x1 -> bn -> relu ----------------
__global__ void stageA_kernel(const float* __restrict__ x,
                              const float* __restrict__ w1, const float* __restrict__ b1,
                              const float* __restrict__ g1, const float* __restrict__ bb1,
                              const float* __restrict__ m1, const float* __restrict__ v1,
                              const float* __restrict__ w2, const float* __restrict__ b2,
                              const float* __restrict__ g2, const float* __restrict__ bb2,
                              const float* __restrict__ m2, const float* __restrict__ v2) {
    __shared__ float s_w1[32 * 64];
    __shared__ float s_a1[32], s_c1[32], s_w2[32];
    __shared__ float s_c2;
    int tid = threadIdx.x;
    for (int i = tid; i < 2048; i += 256) s_w1[i] = w1[i];
    if (tid < 32) {
        float s = g1[tid] * rsqrtf(v1[tid] + 1e-5f);
        s_a1[tid] = s;
        s_c1[tid] = fmaf(b1[tid], s, bb1[tid] - m1[tid] * s);
        float s2 = g2[0] * rsqrtf(v2[0] + 1e-5f);
        s_w2[tid] = w2[tid] * s2;
        if (tid == 0) s_c2 = fmaf(b2[0], s2, bb2[0] - m2[0] * s2);
    }
    __syncthreads();

    int e = blockIdx.x * 256 + tid;   // e = l*12 + d
    if (e >= LSEQ * 12) return;

    float acc[32];
#pragma unroll
    for (int o = 0; o < 32; o++) acc[o] = 0.f;

    const float* xp = x + e;
#pragma unroll 4
    for (int c = 0; c < 64; c++) {
        float xv = xp[(size_t)c * (LSEQ * 12)];
#pragma unroll
        for (int o = 0; o < 32; o++) acc[o] = fmaf(xv, s_w1[o * 64 + c], acc[o]);
    }
    float outv = s_c2;
#pragma unroll
    for (int o = 0; o < 32; o++) {
        float mo = fmaxf(fmaf(acc[o], s_a1[o], s_c1[o]), 0.f);
        outv = fmaf(mo, s_w2[o], outv);
    }
    g_seq[e] = fmaxf(outv, 0.f);
}

// ---------------- GRU gate-input precompute ----------------
// stores {0.5*(ir+bhh_r), 0.5*(iz+bhh_z), inn, 0} -- half factors folded for tanh-based sigmoid
__global__ void gi_kernel(const float* __restrict__ Wih,   // (2,18,12)
                          const float* __restrict__ bih,   // (2,18)
                          const float* __restrict__ bhh) { // (2,18)
    int idx = blockIdx.x * blockDim.x + threadIdx.x;
    if (idx >= 2 * 6 * LSEQ) return;
    int dir = idx / (6 * LSEQ);
    int rem = idx - dir * (6 * LSEQ);
    int t = rem / 6;
    int j = rem % 6;
    int tt = dir ? (LSEQ - 1 - t) : t;

    const float* sr = g_seq + tt * 12;
    float s[12];
#pragma unroll
    for (int d = 0; d < 12; d++) s[d] = sr[d];

    const float* W = Wih + dir * 216;
    float gr = bih[dir * 18 + j]      + bhh[dir * 18 + j];
    float gz = bih[dir * 18 + 6 + j]  + bhh[dir * 18 + 6 + j];
    float gn = bih[dir * 18 + 12 + j];
#pragma unroll
    for (int d = 0; d < 12; d++) {
        gr = fmaf(s[d], W[j * 12 + d], gr);
        gz = fmaf(s[d], W[(6 + j) * 12 + d], gz);
        gn = fmaf(s[d], W[(12 + j) * 12 + d], gn);
    }
    g_gi[dir][t * 6 + j] = make_float4(0.5f * gr, 0.5f * gz, gn, 0.f);
}

// ---------------- Mamba chunked scan (exact math) ----------------
__global__ void mamba_chunk_kernel(const float* __restrict__ ipw,  // (48,12)
                                   const float* __restrict__ cw,   // (24,4)
                                   const float* __restrict__ cb,   // (24)
                                   const float* __restrict__ xpw,  // (33,24)
                                   const float* __restrict__ dtw,  // (24,1)
                                   const float* __restrict__ dtb,  // (24)
                                   const float* __restrict__ A_log) { // (24,16)
    __shared__ float s_xm[(CS + 3) * 24];
    __shared__ float s_u[CS * 24];
    __shared__ float s_B[CS * 16];
    __shared__ float s_delta[CS * 24];
    __shared__ float s_dt[CS];

    int t0 = blockIdx.x * CS;
    int tid = threadIdx.x;  // 384 threads

    for (int idx = tid; idx < (CS + 3) * 24; idx += 384) {
        int r = idx / 24, k = idx % 24;
        int t = t0 + r - 3;
        float v = 0.f;
        if (t >= 0) {
            const float* sr = g_seq + t * 12;
            const float* w = ipw + k * 12;
#pragma unroll
            for (int d = 0; d < 12; d++) v = fmaf(sr[d], w[d], v);
        }
        s_xm[idx] = v;
    }
    __syncthreads();

    for (int idx = tid; idx < CS * 24; idx += 384) {
        int r = idx / 24, k = idx % 24;
        float a = cb[k];
#pragma unroll
        for (int kk = 0; kk < 4; kk++) a = fmaf(cw[k * 4 + kk], s_xm[(r + kk) * 24 + k], a);
        s_u[idx] = fsilu(a);
    }
    __syncthreads();

    if (tid < CS) {
        float a = 0.f;
#pragma unroll
        for (int k = 0; k < 24; k++) a = fmaf(s_u[tid * 24 + k], xpw[k], a);
        s_dt[tid] = a;
    }
    __syncthreads();

    for (int idx = tid; idx < CS * 16; idx += 384) {
        int r = idx / 16, n = idx % 16;
        float a = 0.f;
#pragma unroll
        for (int k = 0; k < 24; k++) a = fmaf(s_u[r * 24 + k], xpw[(1 + n) * 24 + k], a);
        s_B[idx] = a;
    }
    for (int idx = tid; idx < CS * 24; idx += 384) {
        int r = idx / 24, d = idx % 24;
        float zz = fmaf(s_dt[r], dtw[d], dtb[d]);
        s_delta[idx] = (zz > 15.f) ? zz : log1pf(__expf(zz));
    }
    __syncthreads();

    int d = tid >> 4, n = tid & 15;
    float A_dn = -__expf(A_log[d * 16 + n]);
    float h = 0.f, S = 0.f;
    for (int t = 0; t < CS; t++) {
        float dl = s_delta[t * 24 + d];
        float a = __expf(A_dn * dl);
        h = fmaf(a, h, dl * s_B[t * 16 + n] * s_u[t * 24 + d]);
        S += dl;
    }
    g_cA[blockIdx.x * 384 + tid] = __expf(A_dn * S);
    g_cB[blockIdx.x * 384 + tid] = h;
}

// ---------------- Sequential GRU: warp0 = forward, warp1 = backward ----------------
// ALL 32 lanes stay alive and convergent; lanes >= 6 replicate lane 0's work on
// clamped indices and never store. Full 0xffffffff shfl masks -> SHFLs pipeline
// (no per-shfl convergence overhead).
// sigma(x) = 0.5 + 0.5*tanh(x/2); all 0.5 factors pre-folded into gi and W registers.
__global__ void __launch_bounds__(64, 1)
gru_seq_kernel(const float* __restrict__ hidden,  // (2,1,6)
               const float* __restrict__ Whh,     // (2,18,6)
               const float* __restrict__ bhh) {   // (2,18)
    int dir = threadIdx.x >> 5;
    int lane = threadIdx.x & 31;
    int j = (lane < 6) ? lane : 0;   // clamped unit index for lanes >= 6
    bool owner = (lane < 6);

    const float4* __restrict__ gip = g_gi[dir];

    float Wr[6], Wz[6], Wn[6];   // all pre-scaled by 0.5
#pragma unroll
    for (int i = 0; i < 6; i++) {
        Wr[i] = 0.5f * Whh[dir * 108 + j * 6 + i];
        Wz[i] = 0.5f * Whh[dir * 108 + (6 + j) * 6 + i];
        Wn[i] = 0.5f * Whh[dir * 108 + (12 + j) * 6 + i];
    }
    float hbn = 0.5f * bhh[dir * 18 + 12 + j];

    float hself = hidden[dir * 6 + j];
    float h[6];
#pragma unroll
    for (int i = 0; i < 6; i++) h[i] = __shfl_sync(0xffffffffu, hself, i);

    const int TS = 4;
    const int NT = LSEQ / TS;
    float4 buf[TS];
#pragma unroll
    for (int k = 0; k < TS; k++) buf[k] = gip[k * 6 + j];

    for (int tile = 0; tile < NT; ++tile) {
        bool more = (tile + 1) < NT;
        const float4* np = gip + (size_t)(tile + 1) * (TS * 6);

#pragma unroll
        for (int k = 0; k < TS; k++) {
            float4 g = buf[k];
            if (more) buf[k] = np[k * 6 + j];      // prefetch next tile, same slot

            // tree-structured gate sums (hsn binds the critical path)
            float hsn = dot6(Wn, h, hbn);          // 0.5 * (Whh_n . h + bhh_n)
            float sr  = dot6(Wr, h, g.x);          // 0.5 * (ir + hr)
            float sz  = dot6(Wz, h, g.y);          // 0.5 * (iz + hz)

            float tr = tapx(sr);                   // r = 0.5 + 0.5*tr
            float tz = tapx(sz);                   // z = 0.5 + 0.5*tz
            float c  = g.z + hsn;                  // gn + 0.5*sn
            float n  = tapx(fmaf(tr, hsn, c));     // tanh(gn + r*sn)
            float p  = 0.5f * hself;
            float q  = 0.5f * n;
            hself = fmaf(tz, p - q, p + q);        // (1-z)*n + z*h
#pragma unroll
            for (int i = 0; i < 6; i++) h[i] = __shfl_sync(0xffffffffu, hself, i);
            if (k == 0 && tile == 0 && dir == 1 && owner) g_yb0[lane] = hself;
        }
    }
    if (owner) g_hout[dir * 6 + lane] = hself;
}

// ---------------- Final: fold chunk affine maps, compute pred + hidden_out ----------------
__global__ void final_kernel(const float* __restrict__ ipw, const float* __restrict__ cw,
                             const float* __restrict__ cb, const float* __restrict__ xpw,
                             const float* __restrict__ Dp, const float* __restrict__ opw,
                             const float* __restrict__ linw, const float* __restrict__ linb,
                             float* __restrict__ out, int out_size) {
    __shared__ float s_h[384];
    int tid = threadIdx.x;

    float h = 0.f;
#pragma unroll 4
    for (int c = 0; c < NC; c++)
        h = fmaf(g_cA[c * 384 + tid], h, g_cB[c * 384 + tid]);
    s_h[tid] = h;
    __syncthreads();

    if (tid == 0) {
        float xm4[4][24];
        for (int r = 0; r < 4; r++) {
            const float* sr = g_seq + (LSEQ - 4 + r) * 12;
            for (int k = 0; k < 24; k++) {
                float v = 0.f;
                for (int d = 0; d < 12; d++) v = fmaf(sr[d], ipw[k * 12 + d], v);
                xm4[r][k] = v;
            }
        }
        float u[24];
        for (int k = 0; k < 24; k++) {
            float a = cb[k];
            for (int kk = 0; kk < 4; kk++) a = fmaf(cw[k * 4 + kk], xm4[kk][k], a);
            u[k] = fsilu(a);
        }
        float C[16];
        for (int n = 0; n < 16; n++) {
            float a = 0.f;
            for (int k = 0; k < 24; k++) a = fmaf(u[k], xpw[(17 + n) * 24 + k], a);
            C[n] = a;
        }
        float y[24];
        for (int d = 0; d < 24; d++) {
            float a = u[d] * Dp[d];
            for (int n = 0; n < 16; n++) a = fmaf(s_h[d * 16 + n], C[n], a);
            y[d] = a;
        }
        const float* sl = g_seq + (LSEQ - 1) * 12;
        float ym[24];
        for (int d = 0; d < 24; d++) {
            float rres = 0.f;
            for (int dd = 0; dd < 12; dd++) rres = fmaf(sl[dd], ipw[(24 + d) * 12 + dd], rres);
            ym[d] = y[d] * fsilu(rres);
        }
        float pred = linb[0];
        for (int m = 0; m < 12; m++) {
            float o1 = 0.f;
            for (int d = 0; d < 24; d++) o1 = fmaf(ym[d], opw[m * 24 + d], o1);
            float o2 = (m < 6) ? g_hout[m] : g_yb0[m - 6];
            pred = fmaf(o1 + o2, linw[m], pred);
        }
        out[0] = pred;
        if (out_size >= 13) {
            for (int i = 0; i < 6; i++) out[1 + i] = g_hout[i];      // hf
            for (int i = 0; i < 6; i++) out[7 + i] = g_hout[6 + i];  // hb
        }
    }
}

// ---------------- launch ----------------
extern "C" void kernel_launch(void* const* d_in, const int* in_sizes, int n_in,
                              void* d_out, int out_size) {
    const float* x        = (const float*)d_in[0];
    const float* hidden   = (const float*)d_in[1];
    const float* conv1_w  = (const float*)d_in[2];
    const float* conv1_b  = (const float*)d_in[3];
    const float* bn1_g    = (const float*)d_in[4];
    const float* bn1_b    = (const float*)d_in[5];
    const float* bn1_m    = (const float*)d_in[6];
    const float* bn1_v    = (const float*)d_in[7];
    const float* conv2_w  = (const float*)d_in[8];
    const float* conv2_b  = (const float*)d_in[9];
    const float* bn2_g    = (const float*)d_in[10];
    const float* bn2_b    = (const float*)d_in[11];
    const float* bn2_m    = (const float*)d_in[12];
    const float* bn2_v    = (const float*)d_in[13];
    const float* in_proj_w  = (const float*)d_in[14];
    const float* conv1d_w   = (const float*)d_in[15];
    const float* conv1d_b   = (const float*)d_in[16];
    const float* x_proj_w   = (const float*)d_in[17];
    const float* dt_proj_w  = (const float*)d_in[18];
    const float* dt_proj_b  = (const float*)d_in[19];
    const float* A_log      = (const float*)d_in[20];
    const float* Dp         = (const float*)d_in[21];
    const float* out_proj_w = (const float*)d_in[22];
    const float* gru_Wih    = (const float*)d_in[23];
    const float* gru_Whh    = (const float*)d_in[24];
    const float* gru_bih    = (const float*)d_in[25];
    const float* gru_bhh    = (const float*)d_in[26];
    const float* lin_w      = (const float*)d_in[27];
    const float* lin_b      = (const float*)d_in[28];

    stageA_kernel<<<(LSEQ * 12) / 256, 256>>>(x, conv1_w, conv1_b, bn1_g, bn1_b, bn1_m, bn1_v,
                                              conv2_w, conv2_b, bn2_g, bn2_b, bn2_m, bn2_v);
    gi_kernel<<<(2 * 6 * LSEQ + 255) / 256, 256>>>(gru_Wih, gru_bih, gru_bhh);
    mamba_chunk_kernel<<<NC, 384>>>(in_proj_w, conv1d_w, conv1d_b, x_proj_w,
                                    dt_proj_w, dt_proj_b, A_log);
    gru_seq_kernel<<<1, 64>>>(hidden, gru_Whh, gru_bhh);
    final_kernel<<<1, 384>>>(in_proj_w, conv1d_w, conv1d_b, x_proj_w, Dp, out_proj_w,
                             lin_w, lin_b, (float*)d_out, out_size);
}

// round 8
// speedup vs baseline: 1.0509x; 1.0509x over previous
#include <cuda_runtime.h>
#include <math.h>

#define LSEQ 65536
#define CS 128
#define NC 512   // NC*CS == LSEQ

// ---------------- scratch (static __device__, allocation-free) ----------------
__device__ float  g_seq[LSEQ * 12];        // seq[t][d]
__device__ float4 g_gi[2][LSEQ * 6];       // per-dir packed gate inputs {0.5*gr, 0.5*gz, gn, 0}
__device__ float  g_cA[NC * 384];          // per-chunk affine A
__device__ float  g_cB[NC * 384];          // per-chunk affine B
__device__ float  g_hout[12];              // hf[6], hb[6]
__device__ float  g_yb0[6];                // backward GRU output at step 0

__device__ __forceinline__ float fsig(float x) {
    return __fdividef(1.f, 1.f + __expf(-x));
}
__device__ __forceinline__ float fsilu(float x) {
    return x * fsig(x);
}
// single-MUFU tanh (sm_75+); used only in the GRU hot loop
__device__ __forceinline__ float tapx(float x) {
    float y;
    asm("tanh.approx.f32 %0, %1;" : "=f"(y) : "f"(x));
    return y;
}
// 6-element dot + base, tree-structured
__device__ __forceinline__ float dot6(const float* W, const float* h, float base) {
    float a = fmaf(W[0], h[0], base);
    a = fmaf(W[1], h[1], a);
    float b = W[2] * h[2];
    b = fmaf(W[3], h[3], b);
    float c = W[4] * h[4];
    c = fmaf(W[5], h[5], c);
    return a + (b + c);
}

// ---------------- Stage A: fused conv1x1 -> bn -> relu -> conv1x1 -> bn -> relu ----------------
__global__ void stageA_kernel(const float* __restrict__ x,
                              const float* __restrict__ w1, const float* __restrict__ b1,
                              const float* __restrict__ g1, const float* __restrict__ bb1,
                              const float* __restrict__ m1, const float* __restrict__ v1,
                              const float* __restrict__ w2, const float* __restrict__ b2,
                              const float* __restrict__ g2, const float* __restrict__ bb2,
                              const float* __restrict__ m2, const float* __restrict__ v2) {
    __shared__ float s_w1[32 * 64];
    __shared__ float s_a1[32], s_c1[32], s_w2[32];
    __shared__ float s_c2;
    int tid = threadIdx.x;
    for (int i = tid; i < 2048; i += 256) s_w1[i] = w1[i];
    if (tid < 32) {
        float s = g1[tid] * rsqrtf(v1[tid] + 1e-5f);
        s_a1[tid] = s;
        s_c1[tid] = fmaf(b1[tid], s, bb1[tid] - m1[tid] * s);
        float s2 = g2[0] * rsqrtf(v2[0] + 1e-5f);
        s_w2[tid] = w2[tid] * s2;
        if (tid == 0) s_c2 = fmaf(b2[0], s2, bb2[0] - m2[0] * s2);
    }
    __syncthreads();

    int e = blockIdx.x * 256 + tid;   // e = l*12 + d
    if (e >= LSEQ * 12) return;

    float acc[32];
#pragma unroll
    for (int o = 0; o < 32; o++) acc[o] = 0.f;

    const float* xp = x + e;
#pragma unroll 4
    for (int c = 0; c < 64; c++) {
        float xv = xp[(size_t)c * (LSEQ * 12)];
#pragma unroll
        for (int o = 0; o < 32; o++) acc[o] = fmaf(xv, s_w1[o * 64 + c], acc[o]);
    }
    float outv = s_c2;
#pragma unroll
    for (int o = 0; o < 32; o++) {
        float mo = fmaxf(fmaf(acc[o], s_a1[o], s_c1[o]), 0.f);
        outv = fmaf(mo, s_w2[o], outv);
    }
    g_seq[e] = fmaxf(outv, 0.f);
}

// ---------------- GRU gate-input precompute ----------------
// stores {0.5*(ir+bhh_r), 0.5*(iz+bhh_z), inn, 0}
__global__ void gi_kernel(const float* __restrict__ Wih,   // (2,18,12)
                          const float* __restrict__ bih,   // (2,18)
                          const float* __restrict__ bhh) { // (2,18)
    int idx = blockIdx.x * blockDim.x + threadIdx.x;
    if (idx >= 2 * 6 * LSEQ) return;
    int dir = idx / (6 * LSEQ);
    int rem = idx - dir * (6 * LSEQ);
    int t = rem / 6;
    int j = rem % 6;
    int tt = dir ? (LSEQ - 1 - t) : t;

    const float* sr = g_seq + tt * 12;
    float s[12];
#pragma unroll
    for (int d = 0; d < 12; d++) s[d] = sr[d];

    const float* W = Wih + dir * 216;
    float gr = bih[dir * 18 + j]      + bhh[dir * 18 + j];
    float gz = bih[dir * 18 + 6 + j]  + bhh[dir * 18 + 6 + j];
    float gn = bih[dir * 18 + 12 + j];
#pragma unroll
    for (int d = 0; d < 12; d++) {
        gr = fmaf(s[d], W[j * 12 + d], gr);
        gz = fmaf(s[d], W[(6 + j) * 12 + d], gz);
        gn = fmaf(s[d], W[(12 + j) * 12 + d], gn);
    }
    g_gi[dir][t * 6 + j] = make_float4(0.5f * gr, 0.5f * gz, gn, 0.f);
}

// ---------------- Mamba chunked scan (exact math) ----------------
__global__ void mamba_chunk_kernel(const float* __restrict__ ipw,  // (48,12)
                                   const float* __restrict__ cw,   // (24,4)
                                   const float* __restrict__ cb,   // (24)
                                   const float* __restrict__ xpw,  // (33,24)
                                   const float* __restrict__ dtw,  // (24,1)
                                   const float* __restrict__ dtb,  // (24)
                                   const float* __restrict__ A_log) { // (24,16)
    __shared__ float s_xm[(CS + 3) * 24];
    __shared__ float s_u[CS * 24];
    __shared__ float s_B[CS * 16];
    __shared__ float s_delta[CS * 24];
    __shared__ float s_dt[CS];

    int t0 = blockIdx.x * CS;
    int tid = threadIdx.x;  // 384 threads

    for (int idx = tid; idx < (CS + 3) * 24; idx += 384) {
        int r = idx / 24, k = idx % 24;
        int t = t0 + r - 3;
        float v = 0.f;
        if (t >= 0) {
            const float* sr = g_seq + t * 12;
            const float* w = ipw + k * 12;
#pragma unroll
            for (int d = 0; d < 12; d++) v = fmaf(sr[d], w[d], v);
        }
        s_xm[idx] = v;
    }
    __syncthreads();

    for (int idx = tid; idx < CS * 24; idx += 384) {
        int r = idx / 24, k = idx % 24;
        float a = cb[k];
#pragma unroll
        for (int kk = 0; kk < 4; kk++) a = fmaf(cw[k * 4 + kk], s_xm[(r + kk) * 24 + k], a);
        s_u[idx] = fsilu(a);
    }
    __syncthreads();

    if (tid < CS) {
        float a = 0.f;
#pragma unroll
        for (int k = 0; k < 24; k++) a = fmaf(s_u[tid * 24 + k], xpw[k], a);
        s_dt[tid] = a;
    }
    __syncthreads();

    for (int idx = tid; idx < CS * 16; idx += 384) {
        int r = idx / 16, n = idx % 16;
        float a = 0.f;
#pragma unroll
        for (int k = 0; k < 24; k++) a = fmaf(s_u[r * 24 + k], xpw[(1 + n) * 24 + k], a);
        s_B[idx] = a;
    }
    for (int idx = tid; idx < CS * 24; idx += 384) {
        int r = idx / 24, d = idx % 24;
        float zz = fmaf(s_dt[r], dtw[d], dtb[d]);
        s_delta[idx] = (zz > 15.f) ? zz : log1pf(__expf(zz));
    }
    __syncthreads();

    int d = tid >> 4, n = tid & 15;
    float A_dn = -__expf(A_log[d * 16 + n]);
    float h = 0.f, S = 0.f;
    for (int t = 0; t < CS; t++) {
        float dl = s_delta[t * 24 + d];
        float a = __expf(A_dn * dl);
        h = fmaf(a, h, dl * s_B[t * 16 + n] * s_u[t * 24 + d]);
        S += dl;
    }
    g_cA[blockIdx.x * 384 + tid] = __expf(A_dn * S);
    g_cB[blockIdx.x * 384 + tid] = h;
}

// ---------------- Sequential GRU: warp0 = forward, warp1 = backward ----------------
// Lean math (tanh.approx + pre-folded 0.5 factors) + DEEP prefetch:
// TS=8 ping-pong double buffer -> 8..16 loads in flight, load-to-use distance
// >= ~900 cycles, covering DRAM latency. All lanes alive, full shfl masks.
__global__ void __launch_bounds__(64, 1)
gru_seq_kernel(const float* __restrict__ hidden,  // (2,1,6)
               const float* __restrict__ Whh,     // (2,18,6)
               const float* __restrict__ bhh) {   // (2,18)
    int dir = threadIdx.x >> 5;
    int lane = threadIdx.x & 31;
    int j = (lane < 6) ? lane : 0;   // clamped unit index for lanes >= 6
    bool owner = (lane < 6);

    const float4* __restrict__ gip = g_gi[dir];

    float Wr[6], Wz[6], Wn[6];   // all pre-scaled by 0.5
#pragma unroll
    for (int i = 0; i < 6; i++) {
        Wr[i] = 0.5f * Whh[dir * 108 + j * 6 + i];
        Wz[i] = 0.5f * Whh[dir * 108 + (6 + j) * 6 + i];
        Wn[i] = 0.5f * Whh[dir * 108 + (12 + j) * 6 + i];
    }
    float hbn = 0.5f * bhh[dir * 18 + 12 + j];

    float hself = hidden[dir * 6 + j];
    float h[6];
#pragma unroll
    for (int i = 0; i < 6; i++) h[i] = __shfl_sync(0xffffffffu, hself, i);

    const int TS = 8;
    const int NT = LSEQ / TS;   // 8192 (even)
    float4 A[TS], B[TS];

    // preload tile 0 into A
#pragma unroll
    for (int k = 0; k < TS; k++) A[k] = gip[k * 6 + j];

    for (int tile = 0; tile < NT; tile += 2) {
        // issue loads for tile+1 into B (consumed after A)
        {
            const float4* pB = gip + (size_t)(tile + 1) * (TS * 6);
#pragma unroll
            for (int k = 0; k < TS; k++) B[k] = pB[k * 6 + j];
        }
        // consume A  (steps tile*TS .. tile*TS+7)
#pragma unroll
        for (int k = 0; k < TS; k++) {
            float4 g = A[k];
            float hsn = dot6(Wn, h, hbn);
            float sr  = dot6(Wr, h, g.x);
            float sz  = dot6(Wz, h, g.y);
            float tr = tapx(sr);
            float tz = tapx(sz);
            float c  = g.z + hsn;
            float n  = tapx(fmaf(tr, hsn, c));
            float p  = 0.5f * hself;
            float q  = 0.5f * n;
            hself = fmaf(tz, p - q, p + q);
#pragma unroll
            for (int i = 0; i < 6; i++) h[i] = __shfl_sync(0xffffffffu, hself, i);
            if (k == 0 && tile == 0 && dir == 1 && owner) g_yb0[lane] = hself;
        }
        // issue loads for tile+2 into A (consumed after B)
        if (tile + 2 < NT) {
            const float4* pA = gip + (size_t)(tile + 2) * (TS * 6);
#pragma unroll
            for (int k = 0; k < TS; k++) A[k] = pA[k * 6 + j];
        }
        // consume B  (steps (tile+1)*TS .. +7)
#pragma unroll
        for (int k = 0; k < TS; k++) {
            float4 g = B[k];
            float hsn = dot6(Wn, h, hbn);
            float sr  = dot6(Wr, h, g.x);
            float sz  = dot6(Wz, h, g.y);
            float tr = tapx(sr);
            float tz = tapx(sz);
            float c  = g.z + hsn;
            float n  = tapx(fmaf(tr, hsn, c));
            float p  = 0.5f * hself;
            float q  = 0.5f * n;
            hself = fmaf(tz, p - q, p + q);
#pragma unroll
            for (int i = 0; i < 6; i++) h[i] = __shfl_sync(0xffffffffu, hself, i);
        }
    }
    if (owner) g_hout[dir * 6 + lane] = hself;
}

// ---------------- Final: fold chunk affine maps, compute pred + hidden_out ----------------
__global__ void final_kernel(const float* __restrict__ ipw, const float* __restrict__ cw,
                             const float* __restrict__ cb, const float* __restrict__ xpw,
                             const float* __restrict__ Dp, const float* __restrict__ opw,
                             const float* __restrict__ linw, const float* __restrict__ linb,
                             float* __restrict__ out, int out_size) {
    __shared__ float s_h[384];
    int tid = threadIdx.x;

    float h = 0.f;
#pragma unroll 4
    for (int c = 0; c < NC; c++)
        h = fmaf(g_cA[c * 384 + tid], h, g_cB[c * 384 + tid]);
    s_h[tid] = h;
    __syncthreads();

    if (tid == 0) {
        float xm4[4][24];
        for (int r = 0; r < 4; r++) {
            const float* sr = g_seq + (LSEQ - 4 + r) * 12;
            for (int k = 0; k < 24; k++) {
                float v = 0.f;
                for (int d = 0; d < 12; d++) v = fmaf(sr[d], ipw[k * 12 + d], v);
                xm4[r][k] = v;
            }
        }
        float u[24];
        for (int k = 0; k < 24; k++) {
            float a = cb[k];
            for (int kk = 0; kk < 4; kk++) a = fmaf(cw[k * 4 + kk], xm4[kk][k], a);
            u[k] = fsilu(a);
        }
        float C[16];
        for (int n = 0; n < 16; n++) {
            float a = 0.f;
            for (int k = 0; k < 24; k++) a = fmaf(u[k], xpw[(17 + n) * 24 + k], a);
            C[n] = a;
        }
        float y[24];
        for (int d = 0; d < 24; d++) {
            float a = u[d] * Dp[d];
            for (int n = 0; n < 16; n++) a = fmaf(s_h[d * 16 + n], C[n], a);
            y[d] = a;
        }
        const float* sl = g_seq + (LSEQ - 1) * 12;
        float ym[24];
        for (int d = 0; d < 24; d++) {
            float rres = 0.f;
            for (int dd = 0; dd < 12; dd++) rres = fmaf(sl[dd], ipw[(24 + d) * 12 + dd], rres);
            ym[d] = y[d] * fsilu(rres);
        }
        float pred = linb[0];
        for (int m = 0; m < 12; m++) {
            float o1 = 0.f;
            for (int d = 0; d < 24; d++) o1 = fmaf(ym[d], opw[m * 24 + d], o1);
            float o2 = (m < 6) ? g_hout[m] : g_yb0[m - 6];
            pred = fmaf(o1 + o2, linw[m], pred);
        }
        out[0] = pred;
        if (out_size >= 13) {
            for (int i = 0; i < 6; i++) out[1 + i] = g_hout[i];      // hf
            for (int i = 0; i < 6; i++) out[7 + i] = g_hout[6 + i];  // hb
        }
    }
}

// ---------------- launch ----------------
extern "C" void kernel_launch(void* const* d_in, const int* in_sizes, int n_in,
                              void* d_out, int out_size) {
    const float* x        = (const float*)d_in[0];
    const float* hidden   = (const float*)d_in[1];
    const float* conv1_w  = (const float*)d_in[2];
    const float* conv1_b  = (const float*)d_in[3];
    const float* bn1_g    = (const float*)d_in[4];
    const float* bn1_b    = (const float*)d_in[5];
    const float* bn1_m    = (const float*)d_in[6];
    const float* bn1_v    = (const float*)d_in[7];
    const float* conv2_w  = (const float*)d_in[8];
    const float* conv2_b  = (const float*)d_in[9];
    const float* bn2_g    = (const float*)d_in[10];
    const float* bn2_b    = (const float*)d_in[11];
    const float* bn2_m    = (const float*)d_in[12];
    const float* bn2_v    = (const float*)d_in[13];
    const float* in_proj_w  = (const float*)d_in[14];
    const float* conv1d_w   = (const float*)d_in[15];
    const float* conv1d_b   = (const float*)d_in[16];
    const float* x_proj_w   = (const float*)d_in[17];
    const float* dt_proj_w  = (const float*)d_in[18];
    const float* dt_proj_b  = (const float*)d_in[19];
    const float* A_log      = (const float*)d_in[20];
    const float* Dp         = (const float*)d_in[21];
    const float* out_proj_w = (const float*)d_in[22];
    const float* gru_Wih    = (const float*)d_in[23];
    const float* gru_Whh    = (const float*)d_in[24];
    const float* gru_bih    = (const float*)d_in[25];
    const float* gru_bhh    = (const float*)d_in[26];
    const float* lin_w      = (const float*)d_in[27];
    const float* lin_b      = (const float*)d_in[28];

    stageA_kernel<<<(LSEQ * 12) / 256, 256>>>(x, conv1_w, conv1_b, bn1_g, bn1_b, bn1_m, bn1_v,
                                              conv2_w, conv2_b, bn2_g, bn2_b, bn2_m, bn2_v);
    gi_kernel<<<(2 * 6 * LSEQ + 255) / 256, 256>>>(gru_Wih, gru_bih, gru_bhh);
    mamba_chunk_kernel<<<NC, 384>>>(in_proj_w, conv1d_w, conv1d_b, x_proj_w,
                                    dt_proj_w, dt_proj_b, A_log);
    gru_seq_kernel<<<1, 64>>>(hidden, gru_Whh, gru_bhh);
    final_kernel<<<1, 384>>>(in_proj_w, conv1d_w, conv1d_b, x_proj_w, Dp, out_proj_w,
                             lin_w, lin_b, (float*)d_out, out_size);
}